// round 17
// baseline (speedup 1.0000x reference)
#include <cuda_runtime.h>
#include <math.h>

#define NNODES 1024
#define FD 64
#define MAXB 4
#define CAP 64     // endpoints per (b,node) list; Poisson(16) -> P(>64) ~ 1e-18

// ---- scratch (no allocations allowed; statically zero-initialized) ----
// INVARIANT at kernel_launch entry: g_node == 0, g_cntd == 0, g_cnts == 0.
// k_nodeproc re-zeroes g_node after reading; k_attn re-zeroes the counters
// after reading. Invariant restored by the end of every launch.
__device__ float          g_node [MAXB * NNODES * FD];      // scatter accumulator
__device__ float          g_Wh   [MAXB * NNODES * FD];      // Wh = normalize(node)@W
__device__ float          g_f1   [MAXB * NNODES];
__device__ float          g_f2   [MAXB * NNODES];
__device__ int            g_cntd [MAXB * NNODES];           // #flows with dst==node
__device__ int            g_cnts [MAXB * NNODES];           // #flows with src==node
__device__ unsigned short g_listd[MAXB * NNODES * CAP];     // src endpoints
__device__ unsigned short g_lists[MAXB * NNODES * CAP];     // dst endpoints

// ------------------------------------------------------------------
// K1: feature scatter (RED.128) + dual endpoint binning.
// 8 threads per flow, each reducing two float4s. The c2==0 thread does
// the binning: 2 counter atomicAdd + 2 ushort stores (replaces the 2M
// atomicOr that were 2/3 of the L2-atomic ops).
// ------------------------------------------------------------------
__global__ void k_scatter(const float4* __restrict__ ff,
                          const int* __restrict__ src,
                          const int* __restrict__ dst,
                          int B, int S) {
    int t = blockIdx.x * blockDim.x + threadIdx.x;
    int total = B * S * 8;
    if (t >= total) return;
    int flow = t >> 3;
    int c2   = t & 7;                       // float4 pair selector (== lane&7)
    int b    = flow / S;
    int lane = threadIdx.x & 31;

    int d = 0;
    if (c2 == 0) d = __ldg(&dst[flow]);
    d = __shfl_sync(~0u, d, lane & ~7);     // broadcast within 8-lane group

    const float4* fp = ff + (long)flow * 16;
    float4 v0 = fp[c2];
    float4 v1 = fp[c2 + 8];

    float* p = &g_node[(b * NNODES + d) * FD + c2 * 4];
    asm volatile("red.global.add.v4.f32 [%0], {%1,%2,%3,%4};"
                 :: "l"(p), "f"(v0.x), "f"(v0.y), "f"(v0.z), "f"(v0.w)
                 : "memory");
    asm volatile("red.global.add.v4.f32 [%0], {%1,%2,%3,%4};"
                 :: "l"(p + 32), "f"(v1.x), "f"(v1.y), "f"(v1.z), "f"(v1.w)
                 : "memory");

    if (c2 == 0) {
        int sI = __ldg(&src[flow]);
        int nd = b * NNODES + d;
        int ns = b * NNODES + sI;
        int pp = atomicAdd(&g_cntd[nd], 1);
        if (pp < CAP) g_listd[nd * CAP + pp] = (unsigned short)sI;
        int qq = atomicAdd(&g_cnts[ns], 1);
        if (qq < CAP) g_lists[ns * CAP + qq] = (unsigned short)d;
    }
}

// ------------------------------------------------------------------
// K2 (unchanged, measured-good): h = node/||node||; Wh = h@W;
// f1 = Wh·a1; f2 = Wh·a2. One warp per node; re-zeroes g_node.
// ------------------------------------------------------------------
__global__ void k_nodeproc(const float* __restrict__ W,
                           const float* __restrict__ a1,
                           const float* __restrict__ a2,
                           int BN) {
    __shared__ float sW[FD * FD];
    __shared__ float sh[8][FD];
    int tid = threadIdx.x;
    for (int i = tid; i < FD * FD; i += 256) sW[i] = W[i];
    __syncthreads();

    int warp = tid >> 5, lane = tid & 31;
    int n = blockIdx.x * 8 + warp;
    if (n >= BN) return;

    float x0 = g_node[n * FD + lane];
    float x1 = g_node[n * FD + lane + 32];
    g_node[n * FD + lane]      = 0.0f;     // restore invariant
    g_node[n * FD + lane + 32] = 0.0f;

    float ss = x0 * x0 + x1 * x1;
    #pragma unroll
    for (int o = 16; o; o >>= 1) ss += __shfl_xor_sync(~0u, ss, o);
    float inv = 1.0f / fmaxf(sqrtf(ss), 1e-12f);

    sh[warp][lane]      = x0 * inv;
    sh[warp][lane + 32] = x1 * inv;
    __syncwarp();

    float w0 = 0.0f, w1 = 0.0f;
    #pragma unroll
    for (int d = 0; d < FD; d++) {
        float hd = sh[warp][d];
        w0 = fmaf(hd, sW[d * FD + lane],      w0);
        w1 = fmaf(hd, sW[d * FD + lane + 32], w1);
    }
    g_Wh[n * FD + lane]      = w0;
    g_Wh[n * FD + lane + 32] = w1;

    float p1 = w0 * a1[lane] + w1 * a1[lane + 32];
    float p2 = w0 * a2[lane] + w1 * a2[lane + 32];
    #pragma unroll
    for (int o = 16; o; o >>= 1) {
        p1 += __shfl_xor_sync(~0u, p1, o);
        p2 += __shfl_xor_sync(~0u, p2, o);
    }
    if (lane == 0) { g_f1[n] = p1; g_f2[n] = p2; }
}

// ------------------------------------------------------------------
// K3 v7: one block (128 thr) per row.
//  - active set built from the two endpoint lists with FUSED
//    dedup+compaction: smem atomicOr marks the bit; first setter
//    appends j via smem atomicAdd. Thread-parallel (~32 ATOMS total),
//    replaces the serial warp0 scan+bit-walk.
//  - then the measured-good R10 tail: single-exp pass (no max
//    subtraction: logits O(10), fp32-exp-safe; masked entries exactly
//    0 in the reference), block sum, float4 AXPY, elu.
//  - smem ~3KB (jl/pv only need 2*CAP entries) -> high residency.
// ------------------------------------------------------------------
__global__ void k_attn(float4* __restrict__ out) {
    __shared__ unsigned s_words[32];
    __shared__ short  s_jl[2 * CAP];
    __shared__ float  s_pv[2 * CAP];
    __shared__ float  s_red[4];
    __shared__ float4 s_acc[8][16];
    __shared__ int    s_cnt, s_cd, s_cs;

    int row = blockIdx.x;
    int b   = row >> 10;
    int tid = threadIdx.x;
    int warp = tid >> 5, lane = tid & 31;

    const float*  f2  = g_f2 + b * NNODES;
    const float4* Wh4 = (const float4*)(g_Wh + b * NNODES * FD);

    if (tid < 32) s_words[tid] = 0u;
    if (tid == 0) { s_cnt = 0; int c = g_cntd[row]; g_cntd[row] = 0; s_cd = min(c, CAP); }
    if (tid == 1) {            int c = g_cnts[row]; g_cnts[row] = 0; s_cs = min(c, CAP); }
    __syncthreads();
    int cd = s_cd, cs = s_cs;

    // --- fused dedup + compaction from endpoint lists ---
    for (int i = tid; i < cd; i += 128) {
        int e = g_listd[row * CAP + i];
        unsigned bit = 1u << (e & 31);
        unsigned old = atomicOr(&s_words[e >> 5], bit);
        if (!(old & bit)) { int ix = atomicAdd(&s_cnt, 1); s_jl[ix] = (short)e; }
    }
    for (int i = tid; i < cs; i += 128) {
        int e = g_lists[row * CAP + i];
        unsigned bit = 1u << (e & 31);
        unsigned old = atomicOr(&s_words[e >> 5], bit);
        if (!(old & bit)) { int ix = atomicAdd(&s_cnt, 1); s_jl[ix] = (short)e; }
    }
    __syncthreads();
    int cnt = s_cnt;

    int g = tid >> 4, sub = tid & 15;
    float4 acc = make_float4(0.0f, 0.0f, 0.0f, 0.0f);
    float scale;

    if (cnt == 0) {
        // fully masked row: uniform softmax -> mean of all Wh rows
        for (int j = g; j < NNODES; j += 8) {
            float4 v = Wh4[j * 16 + sub];
            acc.x += v.x; acc.y += v.y; acc.z += v.z; acc.w += v.w;
        }
        scale = 1.0f / NNODES;
    } else {
        float f1i = g_f1[row];
        float psum = 0.0f;
        for (int i = tid; i < cnt; i += 128) {     // cnt <= 128: one iter
            int j = s_jl[i];
            float e = f1i + f2[j];
            e = e >= 0.0f ? e : 0.2f * e;
            float p = __expf(e);
            s_pv[i] = p;
            psum += p;
        }
        #pragma unroll
        for (int o = 16; o; o >>= 1) psum += __shfl_xor_sync(~0u, psum, o);
        if (lane == 0) s_red[warp] = psum;
        __syncthreads();
        float s = s_red[0] + s_red[1] + s_red[2] + s_red[3];

        // --- float4 AXPY over compacted list, 8 groups x 16 threads ---
        for (int i = g; i < cnt; i += 8) {
            int j   = s_jl[i];
            float p = s_pv[i];
            float4 v = Wh4[j * 16 + sub];
            acc.x = fmaf(p, v.x, acc.x);
            acc.y = fmaf(p, v.y, acc.y);
            acc.z = fmaf(p, v.z, acc.z);
            acc.w = fmaf(p, v.w, acc.w);
        }
        scale = 1.0f / s;
    }

    s_acc[g][sub] = acc;
    __syncthreads();
    if (tid < 16) {
        float4 r = s_acc[0][tid];
        #pragma unroll
        for (int gg = 1; gg < 8; gg++) {
            float4 v = s_acc[gg][tid];
            r.x += v.x; r.y += v.y; r.z += v.z; r.w += v.w;
        }
        r.x *= scale; r.y *= scale; r.z *= scale; r.w *= scale;
        r.x = r.x > 0.0f ? r.x : expm1f(r.x);
        r.y = r.y > 0.0f ? r.y : expm1f(r.y);
        r.z = r.z > 0.0f ? r.z : expm1f(r.z);
        r.w = r.w > 0.0f ? r.w : expm1f(r.w);
        out[row * 16 + tid] = r;
    }
}

// ------------------------------------------------------------------
extern "C" void kernel_launch(void* const* d_in, const int* in_sizes, int n_in,
                              void* d_out, int out_size) {
    const float* ff  = (const float*)d_in[0];
    const int*   src = (const int*)  d_in[1];
    const int*   dst = (const int*)  d_in[2];
    const float* W   = (const float*)d_in[9];
    const float* a1  = (const float*)d_in[10];
    const float* a2  = (const float*)d_in[11];

    int B = out_size / (NNODES * FD);       // 4
    int S = in_sizes[1] / B;                // 16384
    int BN = B * NNODES;

    int total = B * S * 8;
    k_scatter<<<(total + 255) / 256, 256>>>((const float4*)ff, src, dst, B, S);

    k_nodeproc<<<(BN + 7) / 8, 256>>>(W, a1, a2, BN);

    k_attn<<<BN, 128>>>((float4*)d_out);
}